// round 1
// baseline (speedup 1.0000x reference)
#include <cuda_runtime.h>
#include <math.h>

#define NE   64      // num experts
#define TK   8       // top-k
#define DIM  2048    // hidden dim
#define TM   128     // tokens per block
#define KB   32      // k-chunk

#define XS_STRIDE (TM + 1)   // 129 -> conflict-free STS/LDS for X tile
#define WS_STRIDE 68         // float4-aligned padded row for W tile
#define LS_STRIDE 68         // float4-aligned padded row for logits tile

__device__ __align__(16) float g_bias[NE];
__device__ float g_nbs;
__device__ float g_acc[NE];

// ---------------------------------------------------------------------------
// Prep: adaptive bias from expert loads (depends only on inputs), zero accum.
// ---------------------------------------------------------------------------
__global__ void k_prep(const float* __restrict__ loads, const float* __restrict__ bs)
{
    int e = threadIdx.x;
    __shared__ float s[NE];
    s[e] = loads[e];
    __syncthreads();

    float sum = 0.f;
    #pragma unroll
    for (int i = 0; i < NE; i++) sum += s[i];
    sum = fmaxf(sum, 1e-8f);

    const float t = 1.0f / (float)NE;
    float kl = 0.f;
    #pragma unroll
    for (int i = 0; i < NE; i++) {
        float q = s[i] / sum;
        kl += t * (logf(t) - logf(fmaxf(q, 1e-8f)));
    }
    float adaptive = 1.0f / (1.0f + expf(-10.0f * kl));
    float nbs = 0.9f * bs[0] + 0.1f * adaptive;

    float q = s[e] / sum;
    g_bias[e] = tanhf((q - t) * (float)NE) * nbs;
    g_acc[e] = 0.f;
    if (e == 0) g_nbs = nbs;
}

// ---------------------------------------------------------------------------
// Main: fused GEMM (logits) + noise + bias + top-8 + softmax + load scatter
// ---------------------------------------------------------------------------
__global__ __launch_bounds__(256, 1) void k_router(
    const float* __restrict__ X,      // [ntok, DIM]
    const float* __restrict__ W,      // [NE, DIM]
    const float* __restrict__ noise,  // [ntok, NE]
    float* __restrict__ out,
    int ntok)
{
    constexpr int XS_BYTES = KB * XS_STRIDE * 4;     // 16512
    constexpr int WS_BYTES = KB * WS_STRIDE * 4;     // 8704
    constexpr int LS_BYTES = TM * LS_STRIDE * 4;     // 34816
    constexpr int GEMM_BYTES = XS_BYTES + WS_BYTES;
    constexpr int UNION_BYTES = (GEMM_BYTES > LS_BYTES) ? GEMM_BYTES : LS_BYTES;

    __shared__ __align__(16) unsigned char smem[UNION_BYTES];
    __shared__ float sLoads[NE];

    float* Xs = (float*)smem;                 // [KB][XS_STRIDE]  (transposed: [k][t])
    float* Ws = (float*)(smem + XS_BYTES);    // [KB][WS_STRIDE]  (transposed: [k][e])
    float* Ls = (float*)smem;                 // [TM][LS_STRIDE]  (reuses GEMM smem)

    const int tid = threadIdx.x;
    const int tx = tid & 15;    // expert-group 0..15 (4 experts each)
    const int ty = tid >> 4;    // token-group 0..15 (8 tokens each)
    const int t0 = blockIdx.x * TM;

    float acc[8][4];
    #pragma unroll
    for (int i = 0; i < 8; i++)
        #pragma unroll
        for (int j = 0; j < 4; j++) acc[i][j] = 0.f;

    for (int kb = 0; kb < DIM; kb += KB) {
        // Load X tile: TM x KB = 4096 floats = 1024 float4; 4 per thread.
        #pragma unroll
        for (int u = 0; u < 4; u++) {
            int f  = u * 256 + tid;
            int t  = f >> 3;          // 8 float4 per token-row chunk
            int c4 = (f & 7) * 4;
            float4 v = *(const float4*)(X + (size_t)(t0 + t) * DIM + kb + c4);
            Xs[(c4 + 0) * XS_STRIDE + t] = v.x;
            Xs[(c4 + 1) * XS_STRIDE + t] = v.y;
            Xs[(c4 + 2) * XS_STRIDE + t] = v.z;
            Xs[(c4 + 3) * XS_STRIDE + t] = v.w;
        }
        // Load W tile: NE x KB = 2048 floats = 512 float4; 2 per thread.
        #pragma unroll
        for (int u = 0; u < 2; u++) {
            int f  = u * 256 + tid;
            int e  = f >> 3;
            int c4 = (f & 7) * 4;
            float4 v = *(const float4*)(W + (size_t)e * DIM + kb + c4);
            Ws[(c4 + 0) * WS_STRIDE + e] = v.x;
            Ws[(c4 + 1) * WS_STRIDE + e] = v.y;
            Ws[(c4 + 2) * WS_STRIDE + e] = v.z;
            Ws[(c4 + 3) * WS_STRIDE + e] = v.w;
        }
        __syncthreads();

        #pragma unroll
        for (int k = 0; k < KB; k++) {
            float4 wv = *(const float4*)&Ws[k * WS_STRIDE + tx * 4];
            float xv[8];
            #pragma unroll
            for (int i = 0; i < 8; i++) xv[i] = Xs[k * XS_STRIDE + ty * 8 + i];
            #pragma unroll
            for (int i = 0; i < 8; i++) {
                acc[i][0] = fmaf(xv[i], wv.x, acc[i][0]);
                acc[i][1] = fmaf(xv[i], wv.y, acc[i][1]);
                acc[i][2] = fmaf(xv[i], wv.z, acc[i][2]);
                acc[i][3] = fmaf(xv[i], wv.w, acc[i][3]);
            }
        }
        __syncthreads();
    }

    // Epilogue part 1: logits = acc + 0.01*noise - bias  -> Ls (reuses smem)
    float4 bv = *(const float4*)(&g_bias[tx * 4]);
    #pragma unroll
    for (int i = 0; i < 8; i++) {
        int t = ty * 8 + i;
        float4 nv = *(const float4*)(noise + (size_t)(t0 + t) * NE + tx * 4);
        float4 lv;
        lv.x = acc[i][0] + 0.01f * nv.x - bv.x;
        lv.y = acc[i][1] + 0.01f * nv.y - bv.y;
        lv.z = acc[i][2] + 0.01f * nv.z - bv.z;
        lv.w = acc[i][3] + 0.01f * nv.w - bv.w;
        *(float4*)&Ls[t * LS_STRIDE + tx * 4] = lv;
    }
    if (tid < NE) sLoads[tid] = 0.f;
    __syncthreads();

    // Epilogue part 2: per-token top-8 (stable: lowest index wins ties),
    // softmax over selected, write outputs, accumulate per-expert loads.
    if (tid < TM) {
        const int t = tid;
        float tv[TK];
        int   ti[TK];
        #pragma unroll
        for (int k = 0; k < TK; k++) { tv[k] = -INFINITY; ti[k] = -1; }

        for (int e = 0; e < NE; e++) {
            float v = Ls[t * LS_STRIDE + e];
            if (v > tv[TK - 1]) {           // strict >: earlier equal value stays
                int p = TK - 1;
                while (p > 0 && tv[p - 1] < v) {  // stop at equal -> stable insert
                    tv[p] = tv[p - 1];
                    ti[p] = ti[p - 1];
                    --p;
                }
                tv[p] = v;
                ti[p] = e;
            }
        }

        float m = tv[0];
        float w[TK];
        float s = 0.f;
        #pragma unroll
        for (int k = 0; k < TK; k++) { w[k] = expf(tv[k] - m); s += w[k]; }
        float inv = 1.0f / s;

        size_t gt = (size_t)(t0 + t);
        size_t woff = (size_t)ntok * TK;
        #pragma unroll
        for (int k = 0; k < TK; k++) {
            float wk = w[k] * inv;
            out[gt * TK + k]        = (float)ti[k];
            out[woff + gt * TK + k] = wk;
            atomicAdd(&sLoads[ti[k]], wk);
        }
    }
    __syncthreads();
    if (tid < NE) atomicAdd(&g_acc[tid], sLoads[tid]);
}

// ---------------------------------------------------------------------------
// Final: EMA load update + new bias strength
// ---------------------------------------------------------------------------
__global__ void k_final(const float* __restrict__ loads, float* __restrict__ out, int ntok)
{
    int e = threadIdx.x;
    size_t base = (size_t)ntok * TK * 2;
    float batch = g_acc[e] / (float)ntok;
    out[base + e] = 0.999f * loads[e] + (1.0f - 0.999f) * batch;
    if (e == 0) out[base + NE] = g_nbs;
}

// ---------------------------------------------------------------------------
// Launch
// ---------------------------------------------------------------------------
extern "C" void kernel_launch(void* const* d_in, const int* in_sizes, int n_in,
                              void* d_out, int out_size)
{
    const float* X     = (const float*)d_in[0];  // hidden_states [4,4096,2048]
    const float* W     = (const float*)d_in[1];  // router_w [64,2048]
    const float* loads = (const float*)d_in[2];  // expert_loads [64]
    const float* bs    = (const float*)d_in[3];  // bias_strength [1]
    const float* noise = (const float*)d_in[4];  // noise [16384,64]
    float* out = (float*)d_out;

    int ntok = in_sizes[0] / DIM;

    k_prep<<<1, NE>>>(loads, bs);
    k_router<<<ntok / TM, 256>>>(X, W, noise, out, ntok);
    k_final<<<1, NE>>>(loads, out, ntok);
}